// round 11
// baseline (speedup 1.0000x reference)
#include <cuda_runtime.h>
#include <cstdint>

// Problem constants (fixed by the dataset)
#define BATCH   16
#define C_IN    64
#define HH      32
#define WW      32
#define C_OUT   128
#define NB      2            // batches per block
#define RPW     40           // padded row width: 4 left + 32 + 4 right
#define WROWS   6            // input rows staged per warp (4 outputs + halo)
#define WPLANE  (WROWS*RPW)  // 240 floats: one channel slab per warp
#define WBATCH  (2*WPLANE)   // 480: both channels, one batch
#define WREG    (NB*WBATCH)  // 960: one warp's full region (24 contiguous rows)

// Affine-collapse tables for the 16 ops (T0[h]=0 for h<8, =1 for h>=8 -> folded)
__constant__ float CTA[16]  = {0,0,1,1,0,0,1,1,-1,-1, 0, 0,-1,-1, 0, 0};
__constant__ float CTB[16]  = {0,0,0,0,1,1,1,1,-1,-1,-1,-1, 0, 0, 0, 0};
__constant__ float CTAB[16] = {0,1,-1,0,-1,0,-2,-1, 1, 2, 0, 1, 0, 1,-1, 0};

// 16B async copy global->shared (LDGSTS.128)
__device__ __forceinline__ void cp16(float* dst_smem, const float* src) {
    uint32_t d = (uint32_t)__cvta_generic_to_shared(dst_smem);
    asm volatile("cp.async.cg.shared.global [%0], [%1], 16;\n" :: "r"(d), "l"(src));
}

// gate(a,b) = c0 + ca*a + cb*b + cab*a*b, factored to 3 FMAs
__device__ __forceinline__ float gate3(const float4 k, float a, float b) {
    return fmaf(fmaf(k.w, b, k.y), a, fmaf(k.z, b, k.x));
}

__device__ __forceinline__ float redmax8(float v) {
    v = fmaxf(v, __shfl_xor_sync(0xffffffffu, v, 1));
    v = fmaxf(v, __shfl_xor_sync(0xffffffffu, v, 2));
    v = fmaxf(v, __shfl_xor_sync(0xffffffffu, v, 4));
    return v;
}
__device__ __forceinline__ float redsum8(float v) {
    v += __shfl_xor_sync(0xffffffffu, v, 1);
    v += __shfl_xor_sync(0xffffffffu, v, 2);
    v += __shfl_xor_sync(0xffffffffu, v, 4);
    return v;
}

// ---------------------------------------------------------------------------
// One block per (oc, batch-pair); one WARP per 4 output rows. ZERO block-level
// synchronization: each warp stages its own window with cp.async, computes the
// softmax coefficients warp-parallel in registers (shfl reductions), decodes
// leaf offsets in-warp, and waits only on its own copy groups.
// ---------------------------------------------------------------------------
__global__ void __launch_bounds__(256, 7)
tree_kernel(const float* __restrict__ x,
            const float* __restrict__ w,
            const int*   __restrict__ leaf_idx,
            float*       __restrict__ out)
{
    __shared__ __align__(16) float sm[8 * WREG];   // 30720 B (8 warp slabs)

    const int blk  = blockIdx.x;         // 0..1023
    const int oc   = blk & (C_OUT - 1);
    const int bg2  = (blk >> 7) * NB;    // first batch of this block's pair
    const int tid  = threadIdx.x;
    const int warp = tid >> 5;
    const int lane = tid & 31;

    // --- channels (broadcast LDG; const-div -> mul-hi) ---------------------
    const int chA = __ldg(&leaf_idx[oc * 8 + 0]) / 9;
    const int chB = __ldg(&leaf_idx[oc * 8 + 4]) / 9;

    float* const wbase = sm + warp * WREG;

    // --- side pads: rows 0..23 of the warp region are contiguous ----------
    {
        float4 z = make_float4(0.f, 0.f, 0.f, 0.f);
        #pragma unroll
        for (int i = 0; i < 2; i++) {
            int t = lane + i * 32;                 // 0..63, need 48
            if (t < 48)
                *(float4*)(wbase + (t >> 1) * RPW + (t & 1) * 36) = z;
        }
    }

    // --- per-warp staging: 12 rows x 8 chunks per batch (3 tasks/lane) -----
    {
        float4 z = make_float4(0.f, 0.f, 0.f, 0.f);
        #pragma unroll
        for (int u = 0; u < NB; u++) {
            #pragma unroll
            for (int i = 0; i < 3; i++) {
                int tsk  = lane + i * 32;          // 0..95
                int c    = tsk & 7;
                int r12  = tsk >> 3;               // 0..11 (p*6 + lr)
                int p    = r12 >= 6;
                int lr   = r12 - (p ? 6 : 0);
                int grow = (warp << 2) - 1 + lr;   // global input row
                float* dst = wbase + (u * 12 + r12) * RPW + 4 + c * 4;
                if ((unsigned)grow < 32u) {
                    const float* src = x
                        + (((size_t)(bg2 + u) * C_IN + (p ? chB : chA)) << 10)
                        + grow * 32 + c * 4;
                    cp16(dst, src);
                } else {
                    *(float4*)dst = z;             // halo outside the image
                }
            }
            asm volatile("cp.async.commit_group;\n");
        }
    }

    // --- in-warp leaf decode: lane handles leaf (lane&7), then broadcast ---
    int o[8];
    {
        int ml  = lane & 7;
        int idx = __ldg(&leaf_idx[oc * 8 + ml]);
        int ch  = idx / 9;
        int pos = idx - ch * 9;
        int ki  = pos / 3;
        int kj  = pos - ki * 3;
        int off = (ml >> 2) * WPLANE + ki * RPW + kj + 3;
        #pragma unroll
        for (int i = 0; i < 8; i++)
            o[i] = __shfl_sync(0xffffffffu, off, i) + lane;
    }

    // --- warp-parallel softmax -> affine coefficients ----------------------
    // lane = gate*8 + h; lane handles ops {h, h+8} of gate's 16-way softmax.
    float4 k0, k1, k2, k3;
    {
        int g = lane >> 3;
        int h = lane & 7;
        const float* wp = w + (oc * 7 + g) * 16;   // weights [C_out, 7, 16]
        float w0 = __ldg(wp + h);
        float w1 = __ldg(wp + h + 8);

        float m  = redmax8(fmaxf(w0, w1));         // per-gate max
        float e0 = __expf(w0 - m);
        float e1 = __expf(w1 - m);

        float s   = redsum8(e0 + e1);
        float c0  = redsum8(e1);                   // T0: 0 for h, 1 for h+8
        float ca  = redsum8(fmaf(e0, CTA[h],  e1 * CTA[h + 8]));
        float cb  = redsum8(fmaf(e0, CTB[h],  e1 * CTB[h + 8]));
        float cab = redsum8(fmaf(e0, CTAB[h], e1 * CTAB[h + 8]));

        float inv = 1.f / s;
        c0 *= inv; ca *= inv; cb *= inv; cab *= inv;

        // gather gate q's coefficients from lane q*8
        #define BCAST(q) make_float4(__shfl_sync(0xffffffffu, c0,  (q)*8), \
                                     __shfl_sync(0xffffffffu, ca,  (q)*8), \
                                     __shfl_sync(0xffffffffu, cb,  (q)*8), \
                                     __shfl_sync(0xffffffffu, cab, (q)*8))
        k0 = BCAST(0); k1 = BCAST(1); k2 = BCAST(2); k3 = BCAST(3);
        #undef BCAST
    }

    // 8 leaf base pointers within this warp's slab (lane = output column)
    const float* p0 = wbase + o[0];
    const float* p1 = wbase + o[1];
    const float* p2 = wbase + o[2];
    const float* p3 = wbase + o[3];
    const float* p4 = wbase + o[4];
    const float* p5 = wbase + o[5];
    const float* p6 = wbase + o[6];
    const float* p7 = wbase + o[7];

    float* ob = out + ((size_t)bg2 * C_OUT + oc) * (HH * WW)
                    + (warp << 2) * WW + lane;

    #pragma unroll
    for (int u = 0; u < NB; u++) {
        if (u == 0) { asm volatile("cp.async.wait_group 1;\n"); __syncwarp(); }
        else        { asm volatile("cp.async.wait_group 0;\n"); __syncwarp(); }

        #pragma unroll
        for (int lr = 0; lr < 4; lr++) {
            const int d = u * WBATCH + lr * RPW;   // compile-time after unroll

            float l0 = p0[d], l1 = p1[d];
            float l2 = p2[d], l3 = p3[d];
            float l4 = p4[d], l5 = p5[d];
            float l6 = p6[d], l7 = p7[d];

            // level 0: weight rows 0,1,2,3
            float m0 = gate3(k0, l0, l1);
            float m1 = gate3(k1, l2, l3);
            float m2 = gate3(k2, l4, l5);
            float m3 = gate3(k3, l6, l7);
            // level 1: rows 1,2
            float n0 = gate3(k1, m0, m1);
            float n1 = gate3(k2, m2, m3);
            // level 2: row 3
            float r  = gate3(k3, n0, n1);

            ob[u * (C_OUT * HH * WW) + lr * WW] = r;   // constant offsets
        }
    }
}

extern "C" void kernel_launch(void* const* d_in, const int* in_sizes, int n_in,
                              void* d_out, int out_size)
{
    const float* x   = (const float*)d_in[0];          // [16,64,32,32]
    const float* w   = (const float*)d_in[1];          // [128,7,16]
    const int*   idx = (const int*)d_in[2];            // [128,8]
    float*       out = (float*)d_out;                  // [16,128,32,32]

    tree_kernel<<<(BATCH / NB) * C_OUT, 256>>>(x, w, idx, out);
}